// round 14
// baseline (speedup 1.0000x reference)
#include <cuda_runtime.h>
#include <cuda_fp16.h>

// ---------------------------------------------------------------------------
// Net_25469156065564: PCNN forward. fp16 mma.sync m16n8k16 (fp32 accum),
// ldmatrix feed. Tri conv1 kernel: 3-stage cp.async (R7-proven). Small-K
// conv2a/2b kernels: 5-stage deep-prefetch pipeline (fill-bound fix).
// relu+maxpool(2) fused epilogue, half intermediates, pool3+FC fused.
// ---------------------------------------------------------------------------

#define BATCH 512
#define LEN   100
#define XROWS 104
#define XC    752          // 750 data + 2 pad halves (16B row stride)

#define K1P  768
#define K3P  2304
#define K5P  3776
#define K2AP 320
#define K2BP 640

#define PSTR 304           // P row stride (halves)

__device__ __align__(16) __half g_Xpad[BATCH * XROWS * XC + 128];
__device__ __align__(16) __half g_P [BATCH * 50 * PSTR + 128];
__device__ __align__(16) __half g_A2[BATCH * 52 * 200 + 128];
__device__ __align__(16) __half g_O3[BATCH * 50 * 300 + 128];
__device__ __align__(16) __half g_W1 [128 * K1P];
__device__ __align__(16) __half g_W3 [128 * K3P];
__device__ __align__(16) __half g_W5 [128 * K5P];
__device__ __align__(16) __half g_W2a[256 * K2AP];
__device__ __align__(16) __half g_W2b[384 * K2BP];

// ---------------------------------------------------------------------------
__global__ void prep_weights(const float* __restrict__ w11,
                             const float* __restrict__ w13,
                             const float* __restrict__ w15,
                             const float* __restrict__ w2a,
                             const float* __restrict__ w2b)
{
    int which = blockIdx.y;
    int idx = blockIdx.x * 256 + threadIdx.x;
    if (which == 0) {                       // w11 (100,250,3,1) -> [100][768]
        if (idx >= 100 * K1P) return;
        int o = idx / K1P, k = idx % K1P;
        float v = 0.f;
        if (k < 750) { int h = k / 250, ci = k % 250; v = w11[o * 750 + ci * 3 + h]; }
        g_W1[idx] = __float2half_rn(v);
    } else if (which == 1) {                // w13 (100,250,3,3) -> [100][2304]
        if (idx >= 100 * K3P) return;
        int o = idx / K3P, k = idx % K3P;
        float v = 0.f;
        if (k < 2256) {
            int kw = k / 752, r = k % 752;
            if (r < 750) { int h = r / 250, ci = r % 250; v = w13[o * 2250 + ci * 9 + h * 3 + kw]; }
        }
        g_W3[idx] = __float2half_rn(v);
    } else if (which == 2) {                // w15 (100,250,3,5) -> [100][3776]
        if (idx >= 100 * K5P) return;
        int o = idx / K5P, k = idx % K5P;
        float v = 0.f;
        if (k < 3760) {
            int kw = k / 752, r = k % 752;
            if (r < 750) { int h = r / 250, ci = r % 250; v = w15[o * 3750 + ci * 15 + h * 5 + kw]; }
        }
        g_W5[idx] = __float2half_rn(v);
    } else if (which == 3) {                // w2b (300,200,1,3) -> [300][640]
        if (idx >= 300 * K2BP) return;
        int o = idx / K2BP, k = idx % K2BP;
        float v = 0.f;
        if (k < 600) { int kw = k / 200, c2 = k % 200; v = w2b[o * 600 + c2 * 3 + kw]; }
        g_W2b[idx] = __float2half_rn(v);
    } else {                                // w2a (200,300,1,1) -> [200][320]
        if (idx >= 200 * K2AP) return;
        int o = idx / K2AP, k = idx % K2AP;
        g_W2a[idx] = __float2half_rn((k < 300) ? w2a[o * 300 + k] : 0.f);
    }
}

// ---------------------------------------------------------------------------
__global__ void build_x(const int* __restrict__ tok,
                        const int* __restrict__ p1m,
                        const int* __restrict__ p2m,
                        const float* __restrict__ sdp,
                        const float* __restrict__ wemb,
                        const float* __restrict__ p1e,
                        const float* __restrict__ p2e)
{
    int blk = blockIdx.x;
    int b = blk / LEN, l = blk % LEN;
    int tid = threadIdx.x;
    if (tid >= 125) return;
    int t  = tok[b * LEN + l];
    int p1 = p1m[b * LEN + l];
    int p2 = p2m[b * LEN + l];
    float s = sdp[b * LEN + l];
    __half2* row2 = (__half2*)(g_Xpad + ((long)(b * XROWS + l + 2)) * XC);

    float2 w = *(const float2*)(wemb + (long)t * 250 + 2 * tid);
    row2[tid] = __floats2half2_rn(w.x, w.y);
    row2[250 + tid] = __floats2half2_rn(s * w.x, s * w.y);

    int c0 = 250 + 2 * tid, c1 = c0 + 1;
    float v0 = (c0 < 375) ? p1e[p1 * 125 + (c0 - 250)] : p2e[p2 * 125 + (c0 - 375)];
    float v1 = (c1 < 375) ? p1e[p1 * 125 + (c1 - 250)] : p2e[p2 * 125 + (c1 - 375)];
    row2[125 + tid] = __floats2half2_rn(v0, v1);
}

// ---------------------------------------------------------------------------
// Shared GEMM machinery. CTA 128x128, BK=64 halves, 8 warps (4M x 2N),
// warp tile 32x64, ldmatrix + m16n8k16.
// ---------------------------------------------------------------------------
#define TILEH 9216     // halves per A or B tile (128*72)
#define STAGEH 18432   // halves per stage (A+B)

struct GArgs {
    const __half* W; const float* bias; const __half* X; void* out;
    int M, Kp; long sB; int sL; long oB; int oL;
    int mOff, doRelu, outHalf, fusePool;
};

struct FragCtx {
    int aOff[4]; long bOff[4];
    unsigned aDst[4], bDst[4];
    unsigned aLm[2], bLm[4];
};

template<int LOUT>
__device__ __forceinline__ void setup_ctx(const GArgs& g, int mBase, int nBase,
                                          __half* sm, FragCtx& cx)
{
    int tid = threadIdx.x;
    int lane = tid & 31;
    int warp = tid >> 5;
    int wm = warp & 3;
    int wn = warp >> 2;
    int cj = (tid & 7) * 8, cr = tid >> 3;
#pragma unroll
    for (int i = 0; i < 4; i++) {
        int row = cr + 32 * i;
        cx.aOff[i] = (mBase + row) * g.Kp + cj;
        cx.aDst[i] = (unsigned)__cvta_generic_to_shared(sm + row * 72 + cj);
        int n = nBase + row;
        int bb = n / LOUT, ll = n % LOUT;
        cx.bOff[i] = (long)bb * g.sB + (long)ll * g.sL + cj;
        cx.bDst[i] = (unsigned)__cvta_generic_to_shared(sm + TILEH + row * 72 + cj);
    }
    int arow = (lane & 15);
    int akhi = (lane >> 4) * 8;
#pragma unroll
    for (int mi = 0; mi < 2; mi++) {
        int row = wm * 32 + mi * 16 + arow;
        cx.aLm[mi] = (unsigned)__cvta_generic_to_shared(sm + row * 72 + akhi);
    }
    int bcol = ((lane >> 4) << 3) + (lane & 7);
    int bkhi = ((lane >> 3) & 1) * 8;
#pragma unroll
    for (int ni2 = 0; ni2 < 4; ni2++) {
        int col = wn * 64 + ni2 * 16 + bcol;
        cx.bLm[ni2] = (unsigned)__cvta_generic_to_shared(sm + TILEH + col * 72 + bkhi);
    }
}

#define LOAD_STAGE(cx, ko_, so_)                                                \
    do {                                                                        \
        _Pragma("unroll")                                                       \
        for (int i_ = 0; i_ < 4; i_++) {                                        \
            asm volatile("cp.async.cg.shared.global [%0],[%1],16;"              \
                :: "r"((cx).aDst[i_] + (so_)), "l"(W + (cx).aOff[i_] + (ko_))); \
            asm volatile("cp.async.cg.shared.global [%0],[%1],16;"              \
                :: "r"((cx).bDst[i_] + (so_)), "l"(X + (cx).bOff[i_] + (ko_))); \
        }                                                                       \
    } while (0)

__device__ __forceinline__ void compute_chunk(const FragCtx& cx, unsigned so,
                                              float acc[2][8][4])
{
#pragma unroll
    for (int kk = 0; kk < 4; kk++) {
        unsigned ko = so + kk * 32;
        unsigned af[2][4];
#pragma unroll
        for (int mi = 0; mi < 2; mi++)
            asm volatile("ldmatrix.sync.aligned.m8n8.x4.shared.b16 "
                         "{%0,%1,%2,%3}, [%4];"
                         : "=r"(af[mi][0]), "=r"(af[mi][1]),
                           "=r"(af[mi][2]), "=r"(af[mi][3])
                         : "r"(cx.aLm[mi] + ko));
#pragma unroll
        for (int ni2 = 0; ni2 < 4; ni2++) {
            unsigned b00, b01, b10, b11;
            asm volatile("ldmatrix.sync.aligned.m8n8.x4.shared.b16 "
                         "{%0,%1,%2,%3}, [%4];"
                         : "=r"(b00), "=r"(b01), "=r"(b10), "=r"(b11)
                         : "r"(cx.bLm[ni2] + ko));
#pragma unroll
            for (int mi = 0; mi < 2; mi++) {
                asm volatile(
                    "mma.sync.aligned.m16n8k16.row.col.f32.f16.f16.f32 "
                    "{%0,%1,%2,%3}, {%4,%5,%6,%7}, {%8,%9}, {%0,%1,%2,%3};"
                    : "+f"(acc[mi][2 * ni2][0]), "+f"(acc[mi][2 * ni2][1]),
                      "+f"(acc[mi][2 * ni2][2]), "+f"(acc[mi][2 * ni2][3])
                    : "r"(af[mi][0]), "r"(af[mi][1]),
                      "r"(af[mi][2]), "r"(af[mi][3]),
                      "r"(b00), "r"(b01));
                asm volatile(
                    "mma.sync.aligned.m16n8k16.row.col.f32.f16.f16.f32 "
                    "{%0,%1,%2,%3}, {%4,%5,%6,%7}, {%8,%9}, {%0,%1,%2,%3};"
                    : "+f"(acc[mi][2 * ni2 + 1][0]), "+f"(acc[mi][2 * ni2 + 1][1]),
                      "+f"(acc[mi][2 * ni2 + 1][2]), "+f"(acc[mi][2 * ni2 + 1][3])
                    : "r"(af[mi][0]), "r"(af[mi][1]),
                      "r"(af[mi][2]), "r"(af[mi][3]),
                      "r"(b10), "r"(b11));
            }
        }
    }
}

template<int LOUT>
__device__ __forceinline__ void epilogue(const GArgs& g, int mBase, int nBase,
                                         float acc[2][8][4])
{
    int lane = threadIdx.x & 31;
    int warp = threadIdx.x >> 5;
    int wm = warp & 3, wn = warp >> 2;
    int lr = lane >> 2, lc = lane & 3;
#pragma unroll
    for (int mi = 0; mi < 2; mi++) {
        int r0 = mBase + wm * 32 + mi * 16 + lr;
        int r1 = r0 + 8;
        float bv0 = (r0 < g.M) ? g.bias[r0] : 0.f;
        float bv1 = (r1 < g.M) ? g.bias[r1] : 0.f;
        if (g.fusePool) {
            __half* o = (__half*)g.out;
#pragma unroll
            for (int ni = 0; ni < 8; ni++) {
                int cb = nBase + wn * 64 + ni * 8 + lc * 2;
                int b2 = cb / LOUT, l2 = cb % LOUT;
                long base = (long)b2 * g.oB + (long)(l2 >> 1) * g.oL + g.mOff;
                if (r0 < g.M)
                    o[base + r0] = __float2half_rn(
                        fmaxf(fmaxf(acc[mi][ni][0], acc[mi][ni][1]) + bv0, 0.f));
                if (r1 < g.M)
                    o[base + r1] = __float2half_rn(
                        fmaxf(fmaxf(acc[mi][ni][2], acc[mi][ni][3]) + bv1, 0.f));
            }
        } else {
#pragma unroll
            for (int ni = 0; ni < 8; ni++) {
                int cb = nBase + wn * 64 + ni * 8 + lc * 2;
#pragma unroll
                for (int cc = 0; cc < 2; cc++) {
                    int n = cb + cc;
                    int b2 = n / LOUT, l2 = n % LOUT;
                    long base = (long)b2 * g.oB + (long)l2 * g.oL + g.mOff;
                    float v0 = acc[mi][ni][cc] + bv0;
                    float v1 = acc[mi][ni][2 + cc] + bv1;
                    if (g.doRelu) { v0 = fmaxf(v0, 0.f); v1 = fmaxf(v1, 0.f); }
                    if (g.outHalf) {
                        __half* o = (__half*)g.out;
                        if (r0 < g.M) o[base + r0] = __float2half_rn(v0);
                        if (r1 < g.M) o[base + r1] = __float2half_rn(v1);
                    } else {
                        float* o = (float*)g.out;
                        if (r0 < g.M) o[base + r0] = v0;
                        if (r1 < g.M) o[base + r1] = v1;
                    }
                }
            }
        }
    }
}

// ---- 3-stage body (R7/R13-proven) for conv1 tri ----
template<int LOUT>
__device__ __forceinline__ void gemm_body3(const GArgs g, int mBase, int nBase,
                                           __half* sm)
{
    const __half* __restrict__ W = g.W;
    const __half* __restrict__ X = g.X;
    FragCtx cx;
    setup_ctx<LOUT>(g, mBase, nBase, sm, cx);

    float acc[2][8][4];
#pragma unroll
    for (int i = 0; i < 2; i++)
#pragma unroll
        for (int j = 0; j < 8; j++)
#pragma unroll
            for (int q = 0; q < 4; q++) acc[i][j][q] = 0.f;

    int nCh = g.Kp >> 6;
    const unsigned stageB = (unsigned)STAGEH * 2u;

    LOAD_STAGE(cx, 0, 0u);
    asm volatile("cp.async.commit_group;");
    LOAD_STAGE(cx, 64, stageB);
    asm volatile("cp.async.commit_group;");

    unsigned so = 0;
    for (int c = 0; c < nCh; c++) {
        if (c + 1 < nCh) asm volatile("cp.async.wait_group 1;");
        else             asm volatile("cp.async.wait_group 0;");
        __syncthreads();
        if (c + 2 < nCh) {
            unsigned wrSo = so + 2u * stageB;
            if (wrSo >= 3u * stageB) wrSo -= 3u * stageB;
            LOAD_STAGE(cx, (c + 2) * 64, wrSo);
            asm volatile("cp.async.commit_group;");
        }
        compute_chunk(cx, so, acc);
        so += stageB;
        if (so == 3u * stageB) so = 0;
    }
    epilogue<LOUT>(g, mBase, nBase, acc);
}

// ---- 5-stage deep-prefetch body for short-K GEMMs (conv2a nCh=5, 2b nCh=10)
template<int LOUT>
__device__ __forceinline__ void gemm_body5(const GArgs g, int mBase, int nBase,
                                           __half* sm)
{
    const __half* __restrict__ W = g.W;
    const __half* __restrict__ X = g.X;
    FragCtx cx;
    setup_ctx<LOUT>(g, mBase, nBase, sm, cx);

    float acc[2][8][4];
#pragma unroll
    for (int i = 0; i < 2; i++)
#pragma unroll
        for (int j = 0; j < 8; j++)
#pragma unroll
            for (int q = 0; q < 4; q++) acc[i][j][q] = 0.f;

    int nCh = g.Kp >> 6;
    const unsigned stageB = (unsigned)STAGEH * 2u;

    // prologue: prefetch 4 stages (commit one group each; empty if beyond nCh)
#pragma unroll
    for (int s = 0; s < 4; s++) {
        if (s < nCh) LOAD_STAGE(cx, s * 64, (unsigned)s * stageB);
        asm volatile("cp.async.commit_group;");
    }

    for (int c = 0; c < nCh; c++) {
        // groups committed so far: 4 + c; need group c done -> wait_group 3
        asm volatile("cp.async.wait_group 3;");
        __syncthreads();
        int cn = c + 4;
        if (cn < nCh) {
            unsigned wrSo = (unsigned)(cn % 5) * stageB;
            LOAD_STAGE(cx, cn * 64, wrSo);
        }
        asm volatile("cp.async.commit_group;");   // may be empty (tail)
        compute_chunk(cx, (unsigned)(c % 5) * stageB, acc);
    }
    epilogue<LOUT>(g, mBase, nBase, acc);
}

template<int LOUT>
__global__ __launch_bounds__(256, 1)
void gemm_one5(GArgs g)
{
    extern __shared__ __half sm[];
    gemm_body5<LOUT>(g, blockIdx.y * 128, blockIdx.x * 128, sm);
}

template<int LOUT>
__global__ __launch_bounds__(256, 2)
void gemm_tri(GArgs g0, GArgs g1, GArgs g2)
{
    extern __shared__ __half sm[];
    GArgs g = (blockIdx.y == 0) ? g0 : ((blockIdx.y == 1) ? g1 : g2);
    gemm_body3<LOUT>(g, 0, blockIdx.x * 128, sm);
}

// pool over 50 positions (half O3) + FC chain 300 -> 100 -> 50 -> 15 (fp32)
__global__ void pool_fc(const float* __restrict__ d1w, const float* __restrict__ d1b,
                        const float* __restrict__ d2w, const float* __restrict__ d2b,
                        const float* __restrict__ d3w, const float* __restrict__ d3b,
                        float* __restrict__ out)
{
    __shared__ float h0[300], h1[100], h2[50];
    int b = blockIdx.x, tid = threadIdx.x;
    for (int c = tid; c < 300; c += 128) {
        const __half* src = g_O3 + (long)b * 15000 + c;
        float mx = __half2float(src[0]);
        for (int p = 1; p < 50; p++) mx = fmaxf(mx, __half2float(src[p * 300]));
        h0[c] = mx;
    }
    __syncthreads();
    if (tid < 100) {
        float s = d1b[tid];
        for (int k = 0; k < 300; k++) s += h0[k] * d1w[k * 100 + tid];
        h1[tid] = fmaxf(s, 0.f);
    }
    __syncthreads();
    if (tid < 50) {
        float s = d2b[tid];
        for (int k = 0; k < 100; k++) s += h1[k] * d2w[k * 50 + tid];
        h2[tid] = fmaxf(s, 0.f);
    }
    __syncthreads();
    if (tid < 15) {
        float s = d3b[tid];
        for (int k = 0; k < 50; k++) s += h2[k] * d3w[k * 15 + tid];
        out[b * 15 + tid] = s;
    }
}

extern "C" void kernel_launch(void* const* d_in, const int* in_sizes, int n_in,
                              void* d_out, int out_size)
{
    const int*   tok  = (const int*)  d_in[0];
    const int*   p1m  = (const int*)  d_in[1];
    const int*   p2m  = (const int*)  d_in[2];
    const float* sdp  = (const float*)d_in[3];
    const float* wemb = (const float*)d_in[4];
    const float* p1e  = (const float*)d_in[5];
    const float* p2e  = (const float*)d_in[6];
    const float* w11  = (const float*)d_in[7];
    const float* b11  = (const float*)d_in[8];
    const float* w13  = (const float*)d_in[9];
    const float* b13  = (const float*)d_in[10];
    const float* w15  = (const float*)d_in[11];
    const float* b15  = (const float*)d_in[12];
    const float* w2a  = (const float*)d_in[13];
    const float* b2a  = (const float*)d_in[14];
    const float* w2b  = (const float*)d_in[15];
    const float* b2b  = (const float*)d_in[16];
    const float* d1w  = (const float*)d_in[17];
    const float* d1b  = (const float*)d_in[18];
    const float* d2w  = (const float*)d_in[19];
    const float* d2b  = (const float*)d_in[20];
    const float* d3w  = (const float*)d_in[21];
    const float* d3b  = (const float*)d_in[22];

    __half *Xpad, *P, *A2, *O3, *W1, *W3, *W5, *W2a, *W2b;
    cudaGetSymbolAddress((void**)&Xpad, g_Xpad);
    cudaGetSymbolAddress((void**)&P,   g_P);
    cudaGetSymbolAddress((void**)&A2,  g_A2);
    cudaGetSymbolAddress((void**)&O3,  g_O3);
    cudaGetSymbolAddress((void**)&W1,  g_W1);
    cudaGetSymbolAddress((void**)&W3,  g_W3);
    cudaGetSymbolAddress((void**)&W5,  g_W5);
    cudaGetSymbolAddress((void**)&W2a, g_W2a);
    cudaGetSymbolAddress((void**)&W2b, g_W2b);

    const int SMEM3 = 3 * STAGEH * 2;   // 110592 B
    const int SMEM5 = 5 * STAGEH * 2;   // 184320 B
    cudaFuncSetAttribute(gemm_tri<100>, cudaFuncAttributeMaxDynamicSharedMemorySize, SMEM3);
    cudaFuncSetAttribute(gemm_one5<50>, cudaFuncAttributeMaxDynamicSharedMemorySize, SMEM5);

    prep_weights<<<dim3((100 * K5P + 255) / 256, 5), 256>>>(w11, w13, w15, w2a, w2b);

    build_x<<<BATCH * LEN, 128>>>(tok, p1m, p2m, sdp, wemb, p1e, p2e);

    long sBX = (long)XROWS * XC;

    // conv1 (x3) + relu + pool(2) fused -> P[b][p][PSTR] half, one launch
    GArgs gc5 = { W5, b15, Xpad,          P, 100, K5P, sBX, XC,
                  50L * PSTR, PSTR, 200, 1, 1, 1 };
    GArgs gc3 = { W3, b13, Xpad + XC,     P, 100, K3P, sBX, XC,
                  50L * PSTR, PSTR, 100, 1, 1, 1 };
    GArgs gc1 = { W1, b11, Xpad + 2 * XC, P, 100, K1P, sBX, XC,
                  50L * PSTR, PSTR, 0, 1, 1, 1 };
    gemm_tri<100><<<dim3(400, 3), 256, SMEM3>>>(gc5, gc3, gc1);

    // conv2a (1x1) -> A2 half (padded rows 0,51 stay zero) — 5-stage deep
    GArgs g2a = { W2a, b2a, P, A2 + 200, 200, K2AP, 50L * PSTR, PSTR,
                  10400, 200, 0, 0, 1, 0 };
    gemm_one5<50><<<dim3(200, 2), 256, SMEM5>>>(g2a);

    // conv2b (kw=3, pad=1) + relu -> O3 half — 5-stage deep
    GArgs g2b = { W2b, b2b, A2, O3, 300, K2BP, 10400, 200,
                  15000, 300, 0, 1, 1, 0 };
    gemm_one5<50><<<dim3(200, 3), 256, SMEM5>>>(g2b);

    pool_fc<<<BATCH, 128>>>(d1w, d1b, d2w, d2b, d3w, d3b, (float*)d_out);
}

// round 15
// speedup vs baseline: 1.0170x; 1.0170x over previous
#include <cuda_runtime.h>
#include <cuda_fp16.h>

// ---------------------------------------------------------------------------
// Net_25469156065564: PCNN forward. fp16 mma.sync m16n8k16 (fp32 accum),
// ldmatrix feed, 3-stage cp.async (.cg, single barrier/chunk) — R7-proven
// GEMM config. conv1 trio fused + relu+maxpool(2) epilogue. Non-GEMM path:
// multi-row build_x, MLP-unrolled pool_fc.
// ---------------------------------------------------------------------------

#define BATCH 512
#define LEN   100
#define XROWS 104
#define XC    752          // 750 data + 2 pad halves (16B row stride)

#define K1P  768
#define K3P  2304
#define K5P  3776
#define K2AP 320
#define K2BP 640

#define PSTR 304           // P row stride (halves)

__device__ __align__(16) __half g_Xpad[BATCH * XROWS * XC + 128];
__device__ __align__(16) __half g_P [BATCH * 50 * PSTR + 128];
__device__ __align__(16) __half g_A2[BATCH * 52 * 200 + 128];
__device__ __align__(16) float  g_O3[BATCH * 50 * 300];
__device__ __align__(16) __half g_W1 [128 * K1P];
__device__ __align__(16) __half g_W3 [128 * K3P];
__device__ __align__(16) __half g_W5 [128 * K5P];
__device__ __align__(16) __half g_W2a[256 * K2AP];
__device__ __align__(16) __half g_W2b[384 * K2BP];

// ---------------------------------------------------------------------------
__global__ void prep_weights(const float* __restrict__ w11,
                             const float* __restrict__ w13,
                             const float* __restrict__ w15,
                             const float* __restrict__ w2a,
                             const float* __restrict__ w2b)
{
    int which = blockIdx.y;
    int idx = blockIdx.x * 256 + threadIdx.x;
    if (which == 0) {                       // w11 (100,250,3,1) -> [100][768]
        if (idx >= 100 * K1P) return;
        int o = idx / K1P, k = idx % K1P;
        float v = 0.f;
        if (k < 750) { int h = k / 250, ci = k % 250; v = w11[o * 750 + ci * 3 + h]; }
        g_W1[idx] = __float2half_rn(v);
    } else if (which == 1) {                // w13 (100,250,3,3) -> [100][2304]
        if (idx >= 100 * K3P) return;
        int o = idx / K3P, k = idx % K3P;
        float v = 0.f;
        if (k < 2256) {
            int kw = k / 752, r = k % 752;
            if (r < 750) { int h = r / 250, ci = r % 250; v = w13[o * 2250 + ci * 9 + h * 3 + kw]; }
        }
        g_W3[idx] = __float2half_rn(v);
    } else if (which == 2) {                // w15 (100,250,3,5) -> [100][3776]
        if (idx >= 100 * K5P) return;
        int o = idx / K5P, k = idx % K5P;
        float v = 0.f;
        if (k < 3760) {
            int kw = k / 752, r = k % 752;
            if (r < 750) { int h = r / 250, ci = r % 250; v = w15[o * 3750 + ci * 15 + h * 5 + kw]; }
        }
        g_W5[idx] = __float2half_rn(v);
    } else if (which == 3) {                // w2b (300,200,1,3) -> [300][640]
        if (idx >= 300 * K2BP) return;
        int o = idx / K2BP, k = idx % K2BP;
        float v = 0.f;
        if (k < 600) { int kw = k / 200, c2 = k % 200; v = w2b[o * 600 + c2 * 3 + kw]; }
        g_W2b[idx] = __float2half_rn(v);
    } else {                                // w2a (200,300,1,1) -> [200][320]
        if (idx >= 200 * K2AP) return;
        int o = idx / K2AP, k = idx % K2AP;
        g_W2a[idx] = __float2half_rn((k < 300) ? w2a[o * 300 + k] : 0.f);
    }
}

// ---------------------------------------------------------------------------
// Build Xpad rows 2..101; 4 (b,l) rows per block (512 threads, 125 active per
// 128-thread group). half2 stores, float2 embedding loads.
// ---------------------------------------------------------------------------
__global__ void build_x(const int* __restrict__ tok,
                        const int* __restrict__ p1m,
                        const int* __restrict__ p2m,
                        const float* __restrict__ sdp,
                        const float* __restrict__ wemb,
                        const float* __restrict__ p1e,
                        const float* __restrict__ p2e)
{
    int grp = threadIdx.x >> 7;                 // 0..3
    int tid = threadIdx.x & 127;
    int blk = blockIdx.x * 4 + grp;
    if (blk >= BATCH * LEN || tid >= 125) return;
    int b = blk / LEN, l = blk % LEN;
    int t  = tok[b * LEN + l];
    int p1 = p1m[b * LEN + l];
    int p2 = p2m[b * LEN + l];
    float s = sdp[b * LEN + l];
    __half2* row2 = (__half2*)(g_Xpad + ((long)(b * XROWS + l + 2)) * XC);

    float2 w = *(const float2*)(wemb + (long)t * 250 + 2 * tid);
    row2[tid] = __floats2half2_rn(w.x, w.y);
    row2[250 + tid] = __floats2half2_rn(s * w.x, s * w.y);

    int c0 = 250 + 2 * tid, c1 = c0 + 1;
    float v0 = (c0 < 375) ? p1e[p1 * 125 + (c0 - 250)] : p2e[p2 * 125 + (c0 - 375)];
    float v1 = (c1 < 375) ? p1e[p1 * 125 + (c1 - 250)] : p2e[p2 * 125 + (c1 - 375)];
    row2[125 + tid] = __floats2half2_rn(v0, v1);
}

// ---------------------------------------------------------------------------
// GEMM body. CTA 128x128, BK=64 halves, 8 warps (4M x 2N), warp 32x64.
// 3-stage cp.async (.cg), single __syncthreads per chunk, ldmatrix+m16n8k16.
// (Exact R7 configuration.)
// ---------------------------------------------------------------------------
#define TILEH 9216     // halves per A or B tile (128*72)
#define STAGEH 18432   // halves per stage (A+B)

struct GArgs {
    const __half* W; const float* bias; const __half* X; void* out;
    int M, Kp; long sB; int sL; long oB; int oL;
    int mOff, doRelu, outHalf, fusePool;
};

template<int LOUT>
__device__ __forceinline__ void gemm_body(const GArgs g, int mBase, int nBase,
                                          __half* sm)
{
    const __half* __restrict__ W = g.W;
    const __half* __restrict__ X = g.X;

    int tid = threadIdx.x;
    int lane = tid & 31;
    int warp = tid >> 5;
    int wm = warp & 3;
    int wn = warp >> 2;
    int lr = lane >> 2;
    int lc = lane & 3;

    // cp.async mapping: both tiles 128 rows x 64 halves, 16B chunks.
    int cj = (tid & 7) * 8, cr = tid >> 3;
    int aOff[4];
    long bOff[4];
    unsigned aDst[4], bDst[4];
#pragma unroll
    for (int i = 0; i < 4; i++) {
        int row = cr + 32 * i;
        aOff[i] = (mBase + row) * g.Kp + cj;
        aDst[i] = (unsigned)__cvta_generic_to_shared(sm + row * 72 + cj);
        int n = nBase + row;
        int bb = n / LOUT, ll = n % LOUT;
        bOff[i] = (long)bb * g.sB + (long)ll * g.sL + cj;
        bDst[i] = (unsigned)__cvta_generic_to_shared(sm + TILEH + row * 72 + cj);
    }

    // ldmatrix base addresses (stage 0)
    unsigned aLm[2], bLm[4];
    {
        int arow = (lane & 15);
        int akhi = (lane >> 4) * 8;
#pragma unroll
        for (int mi = 0; mi < 2; mi++) {
            int row = wm * 32 + mi * 16 + arow;
            aLm[mi] = (unsigned)__cvta_generic_to_shared(sm + row * 72 + akhi);
        }
        int bcol = ((lane >> 4) << 3) + (lane & 7);
        int bkhi = ((lane >> 3) & 1) * 8;
#pragma unroll
        for (int ni2 = 0; ni2 < 4; ni2++) {
            int col = wn * 64 + ni2 * 16 + bcol;
            bLm[ni2] = (unsigned)__cvta_generic_to_shared(sm + TILEH + col * 72 + bkhi);
        }
    }

    float acc[2][8][4];
#pragma unroll
    for (int i = 0; i < 2; i++)
#pragma unroll
        for (int j = 0; j < 8; j++)
#pragma unroll
            for (int q = 0; q < 4; q++) acc[i][j][q] = 0.f;

    int nCh = g.Kp >> 6;                 // >= 5 for all our GEMMs
    const unsigned stageB = (unsigned)STAGEH * 2u;

#define LOAD_STAGE(ko_, so_)                                                    \
    do {                                                                        \
        _Pragma("unroll")                                                       \
        for (int i_ = 0; i_ < 4; i_++) {                                        \
            asm volatile("cp.async.cg.shared.global [%0],[%1],16;"              \
                         :: "r"(aDst[i_] + (so_)), "l"(W + aOff[i_] + (ko_)));  \
            asm volatile("cp.async.cg.shared.global [%0],[%1],16;"              \
                         :: "r"(bDst[i_] + (so_)), "l"(X + bOff[i_] + (ko_)));  \
        }                                                                       \
    } while (0)

    // prologue: stages 0,1
    LOAD_STAGE(0, 0u);
    asm volatile("cp.async.commit_group;");
    LOAD_STAGE(64, stageB);
    asm volatile("cp.async.commit_group;");

    unsigned so = 0;                      // read-stage byte offset
    for (int c = 0; c < nCh; c++) {
        if (c + 1 < nCh) asm volatile("cp.async.wait_group 1;");
        else             asm volatile("cp.async.wait_group 0;");
        __syncthreads();

        if (c + 2 < nCh) {
            unsigned wrSo = so + 2u * stageB;
            if (wrSo >= 3u * stageB) wrSo -= 3u * stageB;
            LOAD_STAGE((c + 2) * 64, wrSo);
            asm volatile("cp.async.commit_group;");
        }

#pragma unroll
        for (int kk = 0; kk < 4; kk++) {
            unsigned ko = so + kk * 32;   // 16 halves = 32 bytes
            unsigned af[2][4];
#pragma unroll
            for (int mi = 0; mi < 2; mi++)
                asm volatile("ldmatrix.sync.aligned.m8n8.x4.shared.b16 "
                             "{%0,%1,%2,%3}, [%4];"
                             : "=r"(af[mi][0]), "=r"(af[mi][1]),
                               "=r"(af[mi][2]), "=r"(af[mi][3])
                             : "r"(aLm[mi] + ko));
#pragma unroll
            for (int ni2 = 0; ni2 < 4; ni2++) {
                unsigned b00, b01, b10, b11;
                asm volatile("ldmatrix.sync.aligned.m8n8.x4.shared.b16 "
                             "{%0,%1,%2,%3}, [%4];"
                             : "=r"(b00), "=r"(b01), "=r"(b10), "=r"(b11)
                             : "r"(bLm[ni2] + ko));
#pragma unroll
                for (int mi = 0; mi < 2; mi++) {
                    asm volatile(
                        "mma.sync.aligned.m16n8k16.row.col.f32.f16.f16.f32 "
                        "{%0,%1,%2,%3}, {%4,%5,%6,%7}, {%8,%9}, {%0,%1,%2,%3};"
                        : "+f"(acc[mi][2 * ni2][0]), "+f"(acc[mi][2 * ni2][1]),
                          "+f"(acc[mi][2 * ni2][2]), "+f"(acc[mi][2 * ni2][3])
                        : "r"(af[mi][0]), "r"(af[mi][1]),
                          "r"(af[mi][2]), "r"(af[mi][3]),
                          "r"(b00), "r"(b01));
                    asm volatile(
                        "mma.sync.aligned.m16n8k16.row.col.f32.f16.f16.f32 "
                        "{%0,%1,%2,%3}, {%4,%5,%6,%7}, {%8,%9}, {%0,%1,%2,%3};"
                        : "+f"(acc[mi][2 * ni2 + 1][0]), "+f"(acc[mi][2 * ni2 + 1][1]),
                          "+f"(acc[mi][2 * ni2 + 1][2]), "+f"(acc[mi][2 * ni2 + 1][3])
                        : "r"(af[mi][0]), "r"(af[mi][1]),
                          "r"(af[mi][2]), "r"(af[mi][3]),
                          "r"(b10), "r"(b11));
                }
            }
        }
        so += stageB;
        if (so == 3u * stageB) so = 0;
    }
#undef LOAD_STAGE

    // ---------------- epilogue (direct scatter) ----------------
#pragma unroll
    for (int mi = 0; mi < 2; mi++) {
        int r0 = mBase + wm * 32 + mi * 16 + lr;
        int r1 = r0 + 8;
        float bv0 = (r0 < g.M) ? g.bias[r0] : 0.f;
        float bv1 = (r1 < g.M) ? g.bias[r1] : 0.f;
        if (g.fusePool) {
            __half* o = (__half*)g.out;
#pragma unroll
            for (int ni = 0; ni < 8; ni++) {
                int cb = nBase + wn * 64 + ni * 8 + lc * 2;
                int b2 = cb / LOUT, l2 = cb % LOUT;
                long base = (long)b2 * g.oB + (long)(l2 >> 1) * g.oL + g.mOff;
                if (r0 < g.M)
                    o[base + r0] = __float2half_rn(
                        fmaxf(fmaxf(acc[mi][ni][0], acc[mi][ni][1]) + bv0, 0.f));
                if (r1 < g.M)
                    o[base + r1] = __float2half_rn(
                        fmaxf(fmaxf(acc[mi][ni][2], acc[mi][ni][3]) + bv1, 0.f));
            }
        } else {
#pragma unroll
            for (int ni = 0; ni < 8; ni++) {
                int cb = nBase + wn * 64 + ni * 8 + lc * 2;
#pragma unroll
                for (int cc = 0; cc < 2; cc++) {
                    int n = cb + cc;
                    int b2 = n / LOUT, l2 = n % LOUT;
                    long base = (long)b2 * g.oB + (long)l2 * g.oL + g.mOff;
                    float v0 = acc[mi][ni][cc] + bv0;
                    float v1 = acc[mi][ni][2 + cc] + bv1;
                    if (g.doRelu) { v0 = fmaxf(v0, 0.f); v1 = fmaxf(v1, 0.f); }
                    if (g.outHalf) {
                        __half* o = (__half*)g.out;
                        if (r0 < g.M) o[base + r0] = __float2half_rn(v0);
                        if (r1 < g.M) o[base + r1] = __float2half_rn(v1);
                    } else {
                        float* o = (float*)g.out;
                        if (r0 < g.M) o[base + r0] = v0;
                        if (r1 < g.M) o[base + r1] = v1;
                    }
                }
            }
        }
    }
}

template<int LOUT>
__global__ __launch_bounds__(256, 2)
void gemm_one(GArgs g)
{
    extern __shared__ __half sm[];
    gemm_body<LOUT>(g, blockIdx.y * 128, blockIdx.x * 128, sm);
}

template<int LOUT>
__global__ __launch_bounds__(256, 2)
void gemm_tri(GArgs g0, GArgs g1, GArgs g2)
{
    extern __shared__ __half sm[];
    GArgs g = (blockIdx.y == 0) ? g0 : ((blockIdx.y == 1) ? g1 : g2);
    gemm_body<LOUT>(g, 0, blockIdx.x * 128, sm);
}

// pool over 50 positions (float O3, MLP-unrolled) + FC 300->100->50->15
__global__ void pool_fc(const float* __restrict__ d1w, const float* __restrict__ d1b,
                        const float* __restrict__ d2w, const float* __restrict__ d2b,
                        const float* __restrict__ d3w, const float* __restrict__ d3b,
                        float* __restrict__ out)
{
    __shared__ float h0[300], h1[100], h2[50];
    int b = blockIdx.x, tid = threadIdx.x;
    for (int c = tid; c < 300; c += 128) {
        const float* src = g_O3 + (long)b * 15000 + c;
        // 5 independent partial maxes -> MLP ~5 on the strided loads
        float m0 = src[0],       m1 = src[300],     m2 = src[600];
        float m3 = src[900],     m4 = src[1200];
#pragma unroll
        for (int p = 5; p < 50; p += 5) {
            m0 = fmaxf(m0, src[(p + 0) * 300]);
            m1 = fmaxf(m1, src[(p + 1) * 300]);
            m2 = fmaxf(m2, src[(p + 2) * 300]);
            m3 = fmaxf(m3, src[(p + 3) * 300]);
            m4 = fmaxf(m4, src[(p + 4) * 300]);
        }
        h0[c] = fmaxf(fmaxf(fmaxf(m0, m1), fmaxf(m2, m3)), m4);
    }
    __syncthreads();
    if (tid < 100) {
        float s = d1b[tid];
        for (int k = 0; k < 300; k++) s += h0[k] * d1w[k * 100 + tid];
        h1[tid] = fmaxf(s, 0.f);
    }
    __syncthreads();
    if (tid < 50) {
        float s = d2b[tid];
        for (int k = 0; k < 100; k++) s += h1[k] * d2w[k * 50 + tid];
        h2[tid] = fmaxf(s, 0.f);
    }
    __syncthreads();
    if (tid < 15) {
        float s = d3b[tid];
        for (int k = 0; k < 50; k++) s += h2[k] * d3w[k * 15 + tid];
        out[b * 15 + tid] = s;
    }
}

extern "C" void kernel_launch(void* const* d_in, const int* in_sizes, int n_in,
                              void* d_out, int out_size)
{
    const int*   tok  = (const int*)  d_in[0];
    const int*   p1m  = (const int*)  d_in[1];
    const int*   p2m  = (const int*)  d_in[2];
    const float* sdp  = (const float*)d_in[3];
    const float* wemb = (const float*)d_in[4];
    const float* p1e  = (const float*)d_in[5];
    const float* p2e  = (const float*)d_in[6];
    const float* w11  = (const float*)d_in[7];
    const float* b11  = (const float*)d_in[8];
    const float* w13  = (const float*)d_in[9];
    const float* b13  = (const float*)d_in[10];
    const float* w15  = (const float*)d_in[11];
    const float* b15  = (const float*)d_in[12];
    const float* w2a  = (const float*)d_in[13];
    const float* b2a  = (const float*)d_in[14];
    const float* w2b  = (const float*)d_in[15];
    const float* b2b  = (const float*)d_in[16];
    const float* d1w  = (const float*)d_in[17];
    const float* d1b  = (const float*)d_in[18];
    const float* d2w  = (const float*)d_in[19];
    const float* d2b  = (const float*)d_in[20];
    const float* d3w  = (const float*)d_in[21];
    const float* d3b  = (const float*)d_in[22];

    __half *Xpad, *P, *A2, *W1, *W3, *W5, *W2a, *W2b;
    float *O3;
    cudaGetSymbolAddress((void**)&Xpad, g_Xpad);
    cudaGetSymbolAddress((void**)&P,   g_P);
    cudaGetSymbolAddress((void**)&A2,  g_A2);
    cudaGetSymbolAddress((void**)&O3,  g_O3);
    cudaGetSymbolAddress((void**)&W1,  g_W1);
    cudaGetSymbolAddress((void**)&W3,  g_W3);
    cudaGetSymbolAddress((void**)&W5,  g_W5);
    cudaGetSymbolAddress((void**)&W2a, g_W2a);
    cudaGetSymbolAddress((void**)&W2b, g_W2b);

    const int SMEM = 3 * STAGEH * 2;   // 110592 B (3 stages)
    cudaFuncSetAttribute(gemm_tri<100>, cudaFuncAttributeMaxDynamicSharedMemorySize, SMEM);
    cudaFuncSetAttribute(gemm_one<50>,  cudaFuncAttributeMaxDynamicSharedMemorySize, SMEM);

    prep_weights<<<dim3((100 * K5P + 255) / 256, 5), 256>>>(w11, w13, w15, w2a, w2b);

    build_x<<<(BATCH * LEN + 3) / 4, 512>>>(tok, p1m, p2m, sdp, wemb, p1e, p2e);

    long sBX = (long)XROWS * XC;

    // conv1 (x3) + relu + pool(2) fused -> P[b][p][PSTR] half, one launch
    GArgs gc5 = { W5, b15, Xpad,          P, 100, K5P, sBX, XC,
                  50L * PSTR, PSTR, 200, 1, 1, 1 };
    GArgs gc3 = { W3, b13, Xpad + XC,     P, 100, K3P, sBX, XC,
                  50L * PSTR, PSTR, 100, 1, 1, 1 };
    GArgs gc1 = { W1, b11, Xpad + 2 * XC, P, 100, K1P, sBX, XC,
                  50L * PSTR, PSTR, 0, 1, 1, 1 };
    gemm_tri<100><<<dim3(400, 3), 256, SMEM>>>(gc5, gc3, gc1);

    // conv2a (1x1) -> A2 half (padded rows 0,51 stay zero)
    GArgs g2a = { W2a, b2a, P, A2 + 200, 200, K2AP, 50L * PSTR, PSTR,
                  10400, 200, 0, 0, 1, 0 };
    gemm_one<50><<<dim3(200, 2), 256, SMEM>>>(g2a);

    // conv2b (kw=3, pad=1) + relu -> O3 float
    GArgs g2b = { W2b, b2b, A2, O3, 300, K2BP, 10400, 200,
                  15000, 300, 0, 1, 0, 0 };
    gemm_one<50><<<dim3(200, 3), 256, SMEM>>>(g2b);

    pool_fc<<<BATCH, 128>>>(d1w, d1b, d2w, d2b, d3w, d3b, (float*)d_out);
}

// round 16
// speedup vs baseline: 1.0235x; 1.0064x over previous
#include <cuda_runtime.h>
#include <cuda_fp16.h>

// ---------------------------------------------------------------------------
// Net_25469156065564: PCNN forward — final banked configuration (R7).
// fp16 mma.sync m16n8k16 (fp32 accum), ldmatrix feed, 3-stage cp.async (.cg,
// single barrier/chunk), conv1 trio fused + relu+maxpool(2) epilogue,
// half intermediates (Xpad/P/A2), float O3, pool3+FC fused.
// ---------------------------------------------------------------------------

#define BATCH 512
#define LEN   100
#define XROWS 104
#define XC    752          // 750 data + 2 pad halves (16B row stride)

#define K1P  768
#define K3P  2304
#define K5P  3776
#define K2AP 320
#define K2BP 640

#define PSTR 304           // P row stride (halves)

__device__ __align__(16) __half g_Xpad[BATCH * XROWS * XC + 128];
__device__ __align__(16) __half g_P [BATCH * 50 * PSTR + 128];
__device__ __align__(16) __half g_A2[BATCH * 52 * 200 + 128];
__device__ __align__(16) float  g_O3[BATCH * 50 * 300];
__device__ __align__(16) __half g_W1 [128 * K1P];
__device__ __align__(16) __half g_W3 [128 * K3P];
__device__ __align__(16) __half g_W5 [128 * K5P];
__device__ __align__(16) __half g_W2a[256 * K2AP];
__device__ __align__(16) __half g_W2b[384 * K2BP];

// ---------------------------------------------------------------------------
__global__ void prep_weights(const float* __restrict__ w11,
                             const float* __restrict__ w13,
                             const float* __restrict__ w15,
                             const float* __restrict__ w2a,
                             const float* __restrict__ w2b)
{
    int which = blockIdx.y;
    int idx = blockIdx.x * 256 + threadIdx.x;
    if (which == 0) {                       // w11 (100,250,3,1) -> [100][768]
        if (idx >= 100 * K1P) return;
        int o = idx / K1P, k = idx % K1P;
        float v = 0.f;
        if (k < 750) { int h = k / 250, ci = k % 250; v = w11[o * 750 + ci * 3 + h]; }
        g_W1[idx] = __float2half_rn(v);
    } else if (which == 1) {                // w13 (100,250,3,3) -> [100][2304]
        if (idx >= 100 * K3P) return;
        int o = idx / K3P, k = idx % K3P;
        float v = 0.f;
        if (k < 2256) {
            int kw = k / 752, r = k % 752;
            if (r < 750) { int h = r / 250, ci = r % 250; v = w13[o * 2250 + ci * 9 + h * 3 + kw]; }
        }
        g_W3[idx] = __float2half_rn(v);
    } else if (which == 2) {                // w15 (100,250,3,5) -> [100][3776]
        if (idx >= 100 * K5P) return;
        int o = idx / K5P, k = idx % K5P;
        float v = 0.f;
        if (k < 3760) {
            int kw = k / 752, r = k % 752;
            if (r < 750) { int h = r / 250, ci = r % 250; v = w15[o * 3750 + ci * 15 + h * 5 + kw]; }
        }
        g_W5[idx] = __float2half_rn(v);
    } else if (which == 3) {                // w2b (300,200,1,3) -> [300][640]
        if (idx >= 300 * K2BP) return;
        int o = idx / K2BP, k = idx % K2BP;
        float v = 0.f;
        if (k < 600) { int kw = k / 200, c2 = k % 200; v = w2b[o * 600 + c2 * 3 + kw]; }
        g_W2b[idx] = __float2half_rn(v);
    } else {                                // w2a (200,300,1,1) -> [200][320]
        if (idx >= 200 * K2AP) return;
        int o = idx / K2AP, k = idx % K2AP;
        g_W2a[idx] = __float2half_rn((k < 300) ? w2a[o * 300 + k] : 0.f);
    }
}

// ---------------------------------------------------------------------------
__global__ void build_x(const int* __restrict__ tok,
                        const int* __restrict__ p1m,
                        const int* __restrict__ p2m,
                        const float* __restrict__ sdp,
                        const float* __restrict__ wemb,
                        const float* __restrict__ p1e,
                        const float* __restrict__ p2e)
{
    int blk = blockIdx.x;
    int b = blk / LEN, l = blk % LEN;
    int tid = threadIdx.x;
    if (tid >= 125) return;
    int t  = tok[b * LEN + l];
    int p1 = p1m[b * LEN + l];
    int p2 = p2m[b * LEN + l];
    float s = sdp[b * LEN + l];
    __half2* row2 = (__half2*)(g_Xpad + ((long)(b * XROWS + l + 2)) * XC);

    float2 w = *(const float2*)(wemb + (long)t * 250 + 2 * tid);
    row2[tid] = __floats2half2_rn(w.x, w.y);
    row2[250 + tid] = __floats2half2_rn(s * w.x, s * w.y);

    int c0 = 250 + 2 * tid, c1 = c0 + 1;
    float v0 = (c0 < 375) ? p1e[p1 * 125 + (c0 - 250)] : p2e[p2 * 125 + (c0 - 375)];
    float v1 = (c1 < 375) ? p1e[p1 * 125 + (c1 - 250)] : p2e[p2 * 125 + (c1 - 375)];
    row2[125 + tid] = __floats2half2_rn(v0, v1);
}

// ---------------------------------------------------------------------------
// GEMM body. CTA 128x128, BK=64 halves, 8 warps (4M x 2N), warp 32x64.
// 3-stage cp.async (.cg), single __syncthreads per chunk, ldmatrix+m16n8k16.
// ---------------------------------------------------------------------------
#define TILEH 9216     // halves per A or B tile (128*72)
#define STAGEH 18432   // halves per stage (A+B)

struct GArgs {
    const __half* W; const float* bias; const __half* X; void* out;
    int M, Kp; long sB; int sL; long oB; int oL;
    int mOff, doRelu, outHalf, fusePool;
};

template<int LOUT>
__device__ __forceinline__ void gemm_body(const GArgs g, int mBase, int nBase,
                                          __half* sm)
{
    const __half* __restrict__ W = g.W;
    const __half* __restrict__ X = g.X;

    int tid = threadIdx.x;
    int lane = tid & 31;
    int warp = tid >> 5;
    int wm = warp & 3;
    int wn = warp >> 2;
    int lr = lane >> 2;
    int lc = lane & 3;

    // cp.async mapping: both tiles 128 rows x 64 halves, 16B chunks.
    int cj = (tid & 7) * 8, cr = tid >> 3;
    int aOff[4];
    long bOff[4];
    unsigned aDst[4], bDst[4];
#pragma unroll
    for (int i = 0; i < 4; i++) {
        int row = cr + 32 * i;
        aOff[i] = (mBase + row) * g.Kp + cj;
        aDst[i] = (unsigned)__cvta_generic_to_shared(sm + row * 72 + cj);
        int n = nBase + row;
        int bb = n / LOUT, ll = n % LOUT;
        bOff[i] = (long)bb * g.sB + (long)ll * g.sL + cj;
        bDst[i] = (unsigned)__cvta_generic_to_shared(sm + TILEH + row * 72 + cj);
    }

    // ldmatrix base addresses (stage 0)
    unsigned aLm[2], bLm[4];
    {
        int arow = (lane & 15);
        int akhi = (lane >> 4) * 8;
#pragma unroll
        for (int mi = 0; mi < 2; mi++) {
            int row = wm * 32 + mi * 16 + arow;
            aLm[mi] = (unsigned)__cvta_generic_to_shared(sm + row * 72 + akhi);
        }
        int bcol = ((lane >> 4) << 3) + (lane & 7);
        int bkhi = ((lane >> 3) & 1) * 8;
#pragma unroll
        for (int ni2 = 0; ni2 < 4; ni2++) {
            int col = wn * 64 + ni2 * 16 + bcol;
            bLm[ni2] = (unsigned)__cvta_generic_to_shared(sm + TILEH + col * 72 + bkhi);
        }
    }

    float acc[2][8][4];
#pragma unroll
    for (int i = 0; i < 2; i++)
#pragma unroll
        for (int j = 0; j < 8; j++)
#pragma unroll
            for (int q = 0; q < 4; q++) acc[i][j][q] = 0.f;

    int nCh = g.Kp >> 6;                 // >= 5 for all our GEMMs
    const unsigned stageB = (unsigned)STAGEH * 2u;

#define LOAD_STAGE(ko_, so_)                                                    \
    do {                                                                        \
        _Pragma("unroll")                                                       \
        for (int i_ = 0; i_ < 4; i_++) {                                        \
            asm volatile("cp.async.cg.shared.global [%0],[%1],16;"              \
                         :: "r"(aDst[i_] + (so_)), "l"(W + aOff[i_] + (ko_)));  \
            asm volatile("cp.async.cg.shared.global [%0],[%1],16;"              \
                         :: "r"(bDst[i_] + (so_)), "l"(X + bOff[i_] + (ko_)));  \
        }                                                                       \
    } while (0)

    // prologue: stages 0,1
    LOAD_STAGE(0, 0u);
    asm volatile("cp.async.commit_group;");
    LOAD_STAGE(64, stageB);
    asm volatile("cp.async.commit_group;");

    unsigned so = 0;                      // read-stage byte offset
    for (int c = 0; c < nCh; c++) {
        if (c + 1 < nCh) asm volatile("cp.async.wait_group 1;");
        else             asm volatile("cp.async.wait_group 0;");
        __syncthreads();

        if (c + 2 < nCh) {
            unsigned wrSo = so + 2u * stageB;
            if (wrSo >= 3u * stageB) wrSo -= 3u * stageB;
            LOAD_STAGE((c + 2) * 64, wrSo);
            asm volatile("cp.async.commit_group;");
        }

#pragma unroll
        for (int kk = 0; kk < 4; kk++) {
            unsigned ko = so + kk * 32;   // 16 halves = 32 bytes
            unsigned af[2][4];
#pragma unroll
            for (int mi = 0; mi < 2; mi++)
                asm volatile("ldmatrix.sync.aligned.m8n8.x4.shared.b16 "
                             "{%0,%1,%2,%3}, [%4];"
                             : "=r"(af[mi][0]), "=r"(af[mi][1]),
                               "=r"(af[mi][2]), "=r"(af[mi][3])
                             : "r"(aLm[mi] + ko));
#pragma unroll
            for (int ni2 = 0; ni2 < 4; ni2++) {
                unsigned b00, b01, b10, b11;
                asm volatile("ldmatrix.sync.aligned.m8n8.x4.shared.b16 "
                             "{%0,%1,%2,%3}, [%4];"
                             : "=r"(b00), "=r"(b01), "=r"(b10), "=r"(b11)
                             : "r"(bLm[ni2] + ko));
#pragma unroll
                for (int mi = 0; mi < 2; mi++) {
                    asm volatile(
                        "mma.sync.aligned.m16n8k16.row.col.f32.f16.f16.f32 "
                        "{%0,%1,%2,%3}, {%4,%5,%6,%7}, {%8,%9}, {%0,%1,%2,%3};"
                        : "+f"(acc[mi][2 * ni2][0]), "+f"(acc[mi][2 * ni2][1]),
                          "+f"(acc[mi][2 * ni2][2]), "+f"(acc[mi][2 * ni2][3])
                        : "r"(af[mi][0]), "r"(af[mi][1]),
                          "r"(af[mi][2]), "r"(af[mi][3]),
                          "r"(b00), "r"(b01));
                    asm volatile(
                        "mma.sync.aligned.m16n8k16.row.col.f32.f16.f16.f32 "
                        "{%0,%1,%2,%3}, {%4,%5,%6,%7}, {%8,%9}, {%0,%1,%2,%3};"
                        : "+f"(acc[mi][2 * ni2 + 1][0]), "+f"(acc[mi][2 * ni2 + 1][1]),
                          "+f"(acc[mi][2 * ni2 + 1][2]), "+f"(acc[mi][2 * ni2 + 1][3])
                        : "r"(af[mi][0]), "r"(af[mi][1]),
                          "r"(af[mi][2]), "r"(af[mi][3]),
                          "r"(b10), "r"(b11));
                }
            }
        }
        so += stageB;
        if (so == 3u * stageB) so = 0;
    }
#undef LOAD_STAGE

    // ---------------- epilogue (direct scatter) ----------------
#pragma unroll
    for (int mi = 0; mi < 2; mi++) {
        int r0 = mBase + wm * 32 + mi * 16 + lr;
        int r1 = r0 + 8;
        float bv0 = (r0 < g.M) ? g.bias[r0] : 0.f;
        float bv1 = (r1 < g.M) ? g.bias[r1] : 0.f;
        if (g.fusePool) {
            __half* o = (__half*)g.out;
#pragma unroll
            for (int ni = 0; ni < 8; ni++) {
                int cb = nBase + wn * 64 + ni * 8 + lc * 2;
                int b2 = cb / LOUT, l2 = cb % LOUT;
                long base = (long)b2 * g.oB + (long)(l2 >> 1) * g.oL + g.mOff;
                if (r0 < g.M)
                    o[base + r0] = __float2half_rn(
                        fmaxf(fmaxf(acc[mi][ni][0], acc[mi][ni][1]) + bv0, 0.f));
                if (r1 < g.M)
                    o[base + r1] = __float2half_rn(
                        fmaxf(fmaxf(acc[mi][ni][2], acc[mi][ni][3]) + bv1, 0.f));
            }
        } else {
#pragma unroll
            for (int ni = 0; ni < 8; ni++) {
                int cb = nBase + wn * 64 + ni * 8 + lc * 2;
#pragma unroll
                for (int cc = 0; cc < 2; cc++) {
                    int n = cb + cc;
                    int b2 = n / LOUT, l2 = n % LOUT;
                    long base = (long)b2 * g.oB + (long)l2 * g.oL + g.mOff;
                    float v0 = acc[mi][ni][cc] + bv0;
                    float v1 = acc[mi][ni][2 + cc] + bv1;
                    if (g.doRelu) { v0 = fmaxf(v0, 0.f); v1 = fmaxf(v1, 0.f); }
                    if (g.outHalf) {
                        __half* o = (__half*)g.out;
                        if (r0 < g.M) o[base + r0] = __float2half_rn(v0);
                        if (r1 < g.M) o[base + r1] = __float2half_rn(v1);
                    } else {
                        float* o = (float*)g.out;
                        if (r0 < g.M) o[base + r0] = v0;
                        if (r1 < g.M) o[base + r1] = v1;
                    }
                }
            }
        }
    }
}

template<int LOUT>
__global__ __launch_bounds__(256, 2)
void gemm_one(GArgs g)
{
    extern __shared__ __half sm[];
    gemm_body<LOUT>(g, blockIdx.y * 128, blockIdx.x * 128, sm);
}

template<int LOUT>
__global__ __launch_bounds__(256, 2)
void gemm_tri(GArgs g0, GArgs g1, GArgs g2)
{
    extern __shared__ __half sm[];
    GArgs g = (blockIdx.y == 0) ? g0 : ((blockIdx.y == 1) ? g1 : g2);
    gemm_body<LOUT>(g, 0, blockIdx.x * 128, sm);
}

// pool over 50 positions (float O3, MLP-unrolled) + FC 300->100->50->15
__global__ void pool_fc(const float* __restrict__ d1w, const float* __restrict__ d1b,
                        const float* __restrict__ d2w, const float* __restrict__ d2b,
                        const float* __restrict__ d3w, const float* __restrict__ d3b,
                        float* __restrict__ out)
{
    __shared__ float h0[300], h1[100], h2[50];
    int b = blockIdx.x, tid = threadIdx.x;
    for (int c = tid; c < 300; c += 128) {
        const float* src = g_O3 + (long)b * 15000 + c;
        float m0 = src[0],   m1 = src[300],  m2 = src[600];
        float m3 = src[900], m4 = src[1200];
#pragma unroll
        for (int p = 5; p < 50; p += 5) {
            m0 = fmaxf(m0, src[(p + 0) * 300]);
            m1 = fmaxf(m1, src[(p + 1) * 300]);
            m2 = fmaxf(m2, src[(p + 2) * 300]);
            m3 = fmaxf(m3, src[(p + 3) * 300]);
            m4 = fmaxf(m4, src[(p + 4) * 300]);
        }
        h0[c] = fmaxf(fmaxf(fmaxf(m0, m1), fmaxf(m2, m3)), m4);
    }
    __syncthreads();
    if (tid < 100) {
        float s = d1b[tid];
        for (int k = 0; k < 300; k++) s += h0[k] * d1w[k * 100 + tid];
        h1[tid] = fmaxf(s, 0.f);
    }
    __syncthreads();
    if (tid < 50) {
        float s = d2b[tid];
        for (int k = 0; k < 100; k++) s += h1[k] * d2w[k * 50 + tid];
        h2[tid] = fmaxf(s, 0.f);
    }
    __syncthreads();
    if (tid < 15) {
        float s = d3b[tid];
        for (int k = 0; k < 50; k++) s += h2[k] * d3w[k * 15 + tid];
        out[b * 15 + tid] = s;
    }
}

extern "C" void kernel_launch(void* const* d_in, const int* in_sizes, int n_in,
                              void* d_out, int out_size)
{
    const int*   tok  = (const int*)  d_in[0];
    const int*   p1m  = (const int*)  d_in[1];
    const int*   p2m  = (const int*)  d_in[2];
    const float* sdp  = (const float*)d_in[3];
    const float* wemb = (const float*)d_in[4];
    const float* p1e  = (const float*)d_in[5];
    const float* p2e  = (const float*)d_in[6];
    const float* w11  = (const float*)d_in[7];
    const float* b11  = (const float*)d_in[8];
    const float* w13  = (const float*)d_in[9];
    const float* b13  = (const float*)d_in[10];
    const float* w15  = (const float*)d_in[11];
    const float* b15  = (const float*)d_in[12];
    const float* w2a  = (const float*)d_in[13];
    const float* b2a  = (const float*)d_in[14];
    const float* w2b  = (const float*)d_in[15];
    const float* b2b  = (const float*)d_in[16];
    const float* d1w  = (const float*)d_in[17];
    const float* d1b  = (const float*)d_in[18];
    const float* d2w  = (const float*)d_in[19];
    const float* d2b  = (const float*)d_in[20];
    const float* d3w  = (const float*)d_in[21];
    const float* d3b  = (const float*)d_in[22];

    __half *Xpad, *P, *A2, *W1, *W3, *W5, *W2a, *W2b;
    float *O3;
    cudaGetSymbolAddress((void**)&Xpad, g_Xpad);
    cudaGetSymbolAddress((void**)&P,   g_P);
    cudaGetSymbolAddress((void**)&A2,  g_A2);
    cudaGetSymbolAddress((void**)&O3,  g_O3);
    cudaGetSymbolAddress((void**)&W1,  g_W1);
    cudaGetSymbolAddress((void**)&W3,  g_W3);
    cudaGetSymbolAddress((void**)&W5,  g_W5);
    cudaGetSymbolAddress((void**)&W2a, g_W2a);
    cudaGetSymbolAddress((void**)&W2b, g_W2b);

    const int SMEM = 3 * STAGEH * 2;   // 110592 B (3 stages)
    cudaFuncSetAttribute(gemm_tri<100>, cudaFuncAttributeMaxDynamicSharedMemorySize, SMEM);
    cudaFuncSetAttribute(gemm_one<50>,  cudaFuncAttributeMaxDynamicSharedMemorySize, SMEM);

    prep_weights<<<dim3((100 * K5P + 255) / 256, 5), 256>>>(w11, w13, w15, w2a, w2b);

    build_x<<<BATCH * LEN, 128>>>(tok, p1m, p2m, sdp, wemb, p1e, p2e);

    long sBX = (long)XROWS * XC;

    // conv1 (x3) + relu + pool(2) fused -> P[b][p][PSTR] half, one launch
    GArgs gc5 = { W5, b15, Xpad,          P, 100, K5P, sBX, XC,
                  50L * PSTR, PSTR, 200, 1, 1, 1 };
    GArgs gc3 = { W3, b13, Xpad + XC,     P, 100, K3P, sBX, XC,
                  50L * PSTR, PSTR, 100, 1, 1, 1 };
    GArgs gc1 = { W1, b11, Xpad + 2 * XC, P, 100, K1P, sBX, XC,
                  50L * PSTR, PSTR, 0, 1, 1, 1 };
    gemm_tri<100><<<dim3(400, 3), 256, SMEM>>>(gc5, gc3, gc1);

    // conv2a (1x1) -> A2 half (padded rows 0,51 stay zero)
    GArgs g2a = { W2a, b2a, P, A2 + 200, 200, K2AP, 50L * PSTR, PSTR,
                  10400, 200, 0, 0, 1, 0 };
    gemm_one<50><<<dim3(200, 2), 256, SMEM>>>(g2a);

    // conv2b (kw=3, pad=1) + relu -> O3 float
    GArgs g2b = { W2b, b2b, A2, O3, 300, K2BP, 10400, 200,
                  15000, 300, 0, 1, 0, 0 };
    gemm_one<50><<<dim3(200, 3), 256, SMEM>>>(g2b);

    pool_fc<<<BATCH, 128>>>(d1w, d1b, d2w, d2b, d3w, d3b, (float*)d_out);
}

// round 17
// speedup vs baseline: 1.0278x; 1.0042x over previous
#include <cuda_runtime.h>
#include <cuda_fp16.h>

// ---------------------------------------------------------------------------
// Net_25469156065564: PCNN forward — banked R7 GEMM config + fused init.
// fp16 mma.sync m16n8k16 (fp32 accum), ldmatrix feed, 3-stage cp.async (.cg,
// single barrier/chunk), conv1 trio fused + relu+maxpool(2) epilogue,
// half intermediates (Xpad/P/A2), float O3, pool3+FC fused.
// Init: weight re-layout + Xpad build overlapped in ONE exactly-sized launch.
// ---------------------------------------------------------------------------

#define BATCH 512
#define LEN   100
#define XROWS 104
#define XC    752          // 750 data + 2 pad halves (16B row stride)

#define K1P  768
#define K3P  2304
#define K5P  3776
#define K2AP 320
#define K2BP 640

#define PSTR 304           // P row stride (halves)

__device__ __align__(16) __half g_Xpad[BATCH * XROWS * XC + 128];
__device__ __align__(16) __half g_P [BATCH * 50 * PSTR + 128];
__device__ __align__(16) __half g_A2[BATCH * 52 * 200 + 128];
__device__ __align__(16) float  g_O3[BATCH * 50 * 300];
__device__ __align__(16) __half g_W1 [128 * K1P];
__device__ __align__(16) __half g_W3 [128 * K3P];
__device__ __align__(16) __half g_W5 [128 * K5P];
__device__ __align__(16) __half g_W2a[256 * K2AP];
__device__ __align__(16) __half g_W2b[384 * K2BP];

// ---------------------------------------------------------------------------
// Fused init: one 1D grid, exactly-sized block ranges.
//  [0, N1)            w11 -> g_W1
//  [N1, N1+N3)        w13 -> g_W3
//  ... w15, w2b, w2a
//  [NW, NW+25600)     build_x, 2 (b,l) rows per 256-thread block
// ---------------------------------------------------------------------------
#define NB_W1  300    // ceil(100*768/256)
#define NB_W3  900    // ceil(100*2304/256)
#define NB_W5  1475   // ceil(100*3776/256)
#define NB_W2B 750    // ceil(300*640/256)
#define NB_W2A 250    // ceil(200*320/256)
#define NB_WTS (NB_W1 + NB_W3 + NB_W5 + NB_W2B + NB_W2A)   // 3675
#define NB_BX  25600  // 51200 rows / 2 per block
#define NB_ALL (NB_WTS + NB_BX)

__global__ void init_fused(const float* __restrict__ w11,
                           const float* __restrict__ w13,
                           const float* __restrict__ w15,
                           const float* __restrict__ w2a,
                           const float* __restrict__ w2b,
                           const int* __restrict__ tok,
                           const int* __restrict__ p1m,
                           const int* __restrict__ p2m,
                           const float* __restrict__ sdp,
                           const float* __restrict__ wemb,
                           const float* __restrict__ p1e,
                           const float* __restrict__ p2e)
{
    int blk = blockIdx.x;
    if (blk >= NB_WTS) {
        // ---- build_x: 2 rows per block ----
        int grp = threadIdx.x >> 7;              // 0..1
        int tid = threadIdx.x & 127;
        int rowIdx = (blk - NB_WTS) * 2 + grp;
        if (tid >= 125) return;
        int b = rowIdx / LEN, l = rowIdx % LEN;
        int t  = tok[b * LEN + l];
        int p1 = p1m[b * LEN + l];
        int p2 = p2m[b * LEN + l];
        float s = sdp[b * LEN + l];
        __half2* row2 = (__half2*)(g_Xpad + ((long)(b * XROWS + l + 2)) * XC);

        float2 w = *(const float2*)(wemb + (long)t * 250 + 2 * tid);
        row2[tid] = __floats2half2_rn(w.x, w.y);
        row2[250 + tid] = __floats2half2_rn(s * w.x, s * w.y);

        int c0 = 250 + 2 * tid, c1 = c0 + 1;
        float v0 = (c0 < 375) ? p1e[p1 * 125 + (c0 - 250)] : p2e[p2 * 125 + (c0 - 375)];
        float v1 = (c1 < 375) ? p1e[p1 * 125 + (c1 - 250)] : p2e[p2 * 125 + (c1 - 375)];
        row2[125 + tid] = __floats2half2_rn(v0, v1);
        return;
    }

    // ---- weight re-layout sections ----
    if (blk < NB_W1) {
        int idx = blk * 256 + threadIdx.x;
        if (idx >= 100 * K1P) return;
        int o = idx / K1P, k = idx % K1P;
        float v = 0.f;
        if (k < 750) { int h = k / 250, ci = k % 250; v = w11[o * 750 + ci * 3 + h]; }
        g_W1[idx] = __float2half_rn(v);
    } else if (blk < NB_W1 + NB_W3) {
        int idx = (blk - NB_W1) * 256 + threadIdx.x;
        if (idx >= 100 * K3P) return;
        int o = idx / K3P, k = idx % K3P;
        float v = 0.f;
        if (k < 2256) {
            int kw = k / 752, r = k % 752;
            if (r < 750) { int h = r / 250, ci = r % 250; v = w13[o * 2250 + ci * 9 + h * 3 + kw]; }
        }
        g_W3[idx] = __float2half_rn(v);
    } else if (blk < NB_W1 + NB_W3 + NB_W5) {
        int idx = (blk - NB_W1 - NB_W3) * 256 + threadIdx.x;
        if (idx >= 100 * K5P) return;
        int o = idx / K5P, k = idx % K5P;
        float v = 0.f;
        if (k < 3760) {
            int kw = k / 752, r = k % 752;
            if (r < 750) { int h = r / 250, ci = r % 250; v = w15[o * 3750 + ci * 15 + h * 5 + kw]; }
        }
        g_W5[idx] = __float2half_rn(v);
    } else if (blk < NB_W1 + NB_W3 + NB_W5 + NB_W2B) {
        int idx = (blk - NB_W1 - NB_W3 - NB_W5) * 256 + threadIdx.x;
        if (idx >= 300 * K2BP) return;
        int o = idx / K2BP, k = idx % K2BP;
        float v = 0.f;
        if (k < 600) { int kw = k / 200, c2 = k % 200; v = w2b[o * 600 + c2 * 3 + kw]; }
        g_W2b[idx] = __float2half_rn(v);
    } else {
        int idx = (blk - NB_W1 - NB_W3 - NB_W5 - NB_W2B) * 256 + threadIdx.x;
        if (idx >= 200 * K2AP) return;
        int o = idx / K2AP, k = idx % K2AP;
        g_W2a[idx] = __float2half_rn((k < 300) ? w2a[o * 300 + k] : 0.f);
    }
}

// ---------------------------------------------------------------------------
// GEMM body. CTA 128x128, BK=64 halves, 8 warps (4M x 2N), warp 32x64.
// 3-stage cp.async (.cg), single __syncthreads per chunk, ldmatrix+m16n8k16.
// ---------------------------------------------------------------------------
#define TILEH 9216     // halves per A or B tile (128*72)
#define STAGEH 18432   // halves per stage (A+B)

struct GArgs {
    const __half* W; const float* bias; const __half* X; void* out;
    int M, Kp; long sB; int sL; long oB; int oL;
    int mOff, doRelu, outHalf, fusePool;
};

template<int LOUT>
__device__ __forceinline__ void gemm_body(const GArgs g, int mBase, int nBase,
                                          __half* sm)
{
    const __half* __restrict__ W = g.W;
    const __half* __restrict__ X = g.X;

    int tid = threadIdx.x;
    int lane = tid & 31;
    int warp = tid >> 5;
    int wm = warp & 3;
    int wn = warp >> 2;
    int lr = lane >> 2;
    int lc = lane & 3;

    // cp.async mapping: both tiles 128 rows x 64 halves, 16B chunks.
    int cj = (tid & 7) * 8, cr = tid >> 3;
    int aOff[4];
    long bOff[4];
    unsigned aDst[4], bDst[4];
#pragma unroll
    for (int i = 0; i < 4; i++) {
        int row = cr + 32 * i;
        aOff[i] = (mBase + row) * g.Kp + cj;
        aDst[i] = (unsigned)__cvta_generic_to_shared(sm + row * 72 + cj);
        int n = nBase + row;
        int bb = n / LOUT, ll = n % LOUT;
        bOff[i] = (long)bb * g.sB + (long)ll * g.sL + cj;
        bDst[i] = (unsigned)__cvta_generic_to_shared(sm + TILEH + row * 72 + cj);
    }

    // ldmatrix base addresses (stage 0)
    unsigned aLm[2], bLm[4];
    {
        int arow = (lane & 15);
        int akhi = (lane >> 4) * 8;
#pragma unroll
        for (int mi = 0; mi < 2; mi++) {
            int row = wm * 32 + mi * 16 + arow;
            aLm[mi] = (unsigned)__cvta_generic_to_shared(sm + row * 72 + akhi);
        }
        int bcol = ((lane >> 4) << 3) + (lane & 7);
        int bkhi = ((lane >> 3) & 1) * 8;
#pragma unroll
        for (int ni2 = 0; ni2 < 4; ni2++) {
            int col = wn * 64 + ni2 * 16 + bcol;
            bLm[ni2] = (unsigned)__cvta_generic_to_shared(sm + TILEH + col * 72 + bkhi);
        }
    }

    float acc[2][8][4];
#pragma unroll
    for (int i = 0; i < 2; i++)
#pragma unroll
        for (int j = 0; j < 8; j++)
#pragma unroll
            for (int q = 0; q < 4; q++) acc[i][j][q] = 0.f;

    int nCh = g.Kp >> 6;                 // >= 5 for all our GEMMs
    const unsigned stageB = (unsigned)STAGEH * 2u;

#define LOAD_STAGE(ko_, so_)                                                    \
    do {                                                                        \
        _Pragma("unroll")                                                       \
        for (int i_ = 0; i_ < 4; i_++) {                                        \
            asm volatile("cp.async.cg.shared.global [%0],[%1],16;"              \
                         :: "r"(aDst[i_] + (so_)), "l"(W + aOff[i_] + (ko_)));  \
            asm volatile("cp.async.cg.shared.global [%0],[%1],16;"              \
                         :: "r"(bDst[i_] + (so_)), "l"(X + bOff[i_] + (ko_)));  \
        }                                                                       \
    } while (0)

    // prologue: stages 0,1
    LOAD_STAGE(0, 0u);
    asm volatile("cp.async.commit_group;");
    LOAD_STAGE(64, stageB);
    asm volatile("cp.async.commit_group;");

    unsigned so = 0;                      // read-stage byte offset
    for (int c = 0; c < nCh; c++) {
        if (c + 1 < nCh) asm volatile("cp.async.wait_group 1;");
        else             asm volatile("cp.async.wait_group 0;");
        __syncthreads();

        if (c + 2 < nCh) {
            unsigned wrSo = so + 2u * stageB;
            if (wrSo >= 3u * stageB) wrSo -= 3u * stageB;
            LOAD_STAGE((c + 2) * 64, wrSo);
            asm volatile("cp.async.commit_group;");
        }

#pragma unroll
        for (int kk = 0; kk < 4; kk++) {
            unsigned ko = so + kk * 32;   // 16 halves = 32 bytes
            unsigned af[2][4];
#pragma unroll
            for (int mi = 0; mi < 2; mi++)
                asm volatile("ldmatrix.sync.aligned.m8n8.x4.shared.b16 "
                             "{%0,%1,%2,%3}, [%4];"
                             : "=r"(af[mi][0]), "=r"(af[mi][1]),
                               "=r"(af[mi][2]), "=r"(af[mi][3])
                             : "r"(aLm[mi] + ko));
#pragma unroll
            for (int ni2 = 0; ni2 < 4; ni2++) {
                unsigned b00, b01, b10, b11;
                asm volatile("ldmatrix.sync.aligned.m8n8.x4.shared.b16 "
                             "{%0,%1,%2,%3}, [%4];"
                             : "=r"(b00), "=r"(b01), "=r"(b10), "=r"(b11)
                             : "r"(bLm[ni2] + ko));
#pragma unroll
                for (int mi = 0; mi < 2; mi++) {
                    asm volatile(
                        "mma.sync.aligned.m16n8k16.row.col.f32.f16.f16.f32 "
                        "{%0,%1,%2,%3}, {%4,%5,%6,%7}, {%8,%9}, {%0,%1,%2,%3};"
                        : "+f"(acc[mi][2 * ni2][0]), "+f"(acc[mi][2 * ni2][1]),
                          "+f"(acc[mi][2 * ni2][2]), "+f"(acc[mi][2 * ni2][3])
                        : "r"(af[mi][0]), "r"(af[mi][1]),
                          "r"(af[mi][2]), "r"(af[mi][3]),
                          "r"(b00), "r"(b01));
                    asm volatile(
                        "mma.sync.aligned.m16n8k16.row.col.f32.f16.f16.f32 "
                        "{%0,%1,%2,%3}, {%4,%5,%6,%7}, {%8,%9}, {%0,%1,%2,%3};"
                        : "+f"(acc[mi][2 * ni2 + 1][0]), "+f"(acc[mi][2 * ni2 + 1][1]),
                          "+f"(acc[mi][2 * ni2 + 1][2]), "+f"(acc[mi][2 * ni2 + 1][3])
                        : "r"(af[mi][0]), "r"(af[mi][1]),
                          "r"(af[mi][2]), "r"(af[mi][3]),
                          "r"(b10), "r"(b11));
                }
            }
        }
        so += stageB;
        if (so == 3u * stageB) so = 0;
    }
#undef LOAD_STAGE

    // ---------------- epilogue (direct scatter) ----------------
#pragma unroll
    for (int mi = 0; mi < 2; mi++) {
        int r0 = mBase + wm * 32 + mi * 16 + lr;
        int r1 = r0 + 8;
        float bv0 = (r0 < g.M) ? g.bias[r0] : 0.f;
        float bv1 = (r1 < g.M) ? g.bias[r1] : 0.f;
        if (g.fusePool) {
            __half* o = (__half*)g.out;
#pragma unroll
            for (int ni = 0; ni < 8; ni++) {
                int cb = nBase + wn * 64 + ni * 8 + lc * 2;
                int b2 = cb / LOUT, l2 = cb % LOUT;
                long base = (long)b2 * g.oB + (long)(l2 >> 1) * g.oL + g.mOff;
                if (r0 < g.M)
                    o[base + r0] = __float2half_rn(
                        fmaxf(fmaxf(acc[mi][ni][0], acc[mi][ni][1]) + bv0, 0.f));
                if (r1 < g.M)
                    o[base + r1] = __float2half_rn(
                        fmaxf(fmaxf(acc[mi][ni][2], acc[mi][ni][3]) + bv1, 0.f));
            }
        } else {
#pragma unroll
            for (int ni = 0; ni < 8; ni++) {
                int cb = nBase + wn * 64 + ni * 8 + lc * 2;
#pragma unroll
                for (int cc = 0; cc < 2; cc++) {
                    int n = cb + cc;
                    int b2 = n / LOUT, l2 = n % LOUT;
                    long base = (long)b2 * g.oB + (long)l2 * g.oL + g.mOff;
                    float v0 = acc[mi][ni][cc] + bv0;
                    float v1 = acc[mi][ni][2 + cc] + bv1;
                    if (g.doRelu) { v0 = fmaxf(v0, 0.f); v1 = fmaxf(v1, 0.f); }
                    if (g.outHalf) {
                        __half* o = (__half*)g.out;
                        if (r0 < g.M) o[base + r0] = __float2half_rn(v0);
                        if (r1 < g.M) o[base + r1] = __float2half_rn(v1);
                    } else {
                        float* o = (float*)g.out;
                        if (r0 < g.M) o[base + r0] = v0;
                        if (r1 < g.M) o[base + r1] = v1;
                    }
                }
            }
        }
    }
}

template<int LOUT>
__global__ __launch_bounds__(256, 2)
void gemm_one(GArgs g)
{
    extern __shared__ __half sm[];
    gemm_body<LOUT>(g, blockIdx.y * 128, blockIdx.x * 128, sm);
}

template<int LOUT>
__global__ __launch_bounds__(256, 2)
void gemm_tri(GArgs g0, GArgs g1, GArgs g2)
{
    extern __shared__ __half sm[];
    GArgs g = (blockIdx.y == 0) ? g0 : ((blockIdx.y == 1) ? g1 : g2);
    gemm_body<LOUT>(g, 0, blockIdx.x * 128, sm);
}

// pool over 50 positions (float O3, MLP-unrolled) + FC 300->100->50->15
__global__ void pool_fc(const float* __restrict__ d1w, const float* __restrict__ d1b,
                        const float* __restrict__ d2w, const float* __restrict__ d2b,
                        const float* __restrict__ d3w, const float* __restrict__ d3b,
                        float* __restrict__ out)
{
    __shared__ float h0[300], h1[100], h2[50];
    int b = blockIdx.x, tid = threadIdx.x;
    for (int c = tid; c < 300; c += 128) {
        const float* src = g_O3 + (long)b * 15000 + c;
        float m0 = src[0],   m1 = src[300],  m2 = src[600];
        float m3 = src[900], m4 = src[1200];
#pragma unroll
        for (int p = 5; p < 50; p += 5) {
            m0 = fmaxf(m0, src[(p + 0) * 300]);
            m1 = fmaxf(m1, src[(p + 1) * 300]);
            m2 = fmaxf(m2, src[(p + 2) * 300]);
            m3 = fmaxf(m3, src[(p + 3) * 300]);
            m4 = fmaxf(m4, src[(p + 4) * 300]);
        }
        h0[c] = fmaxf(fmaxf(fmaxf(m0, m1), fmaxf(m2, m3)), m4);
    }
    __syncthreads();
    if (tid < 100) {
        float s = d1b[tid];
        for (int k = 0; k < 300; k++) s += h0[k] * d1w[k * 100 + tid];
        h1[tid] = fmaxf(s, 0.f);
    }
    __syncthreads();
    if (tid < 50) {
        float s = d2b[tid];
        for (int k = 0; k < 100; k++) s += h1[k] * d2w[k * 50 + tid];
        h2[tid] = fmaxf(s, 0.f);
    }
    __syncthreads();
    if (tid < 15) {
        float s = d3b[tid];
        for (int k = 0; k < 50; k++) s += h2[k] * d3w[k * 15 + tid];
        out[b * 15 + tid] = s;
    }
}

extern "C" void kernel_launch(void* const* d_in, const int* in_sizes, int n_in,
                              void* d_out, int out_size)
{
    const int*   tok  = (const int*)  d_in[0];
    const int*   p1m  = (const int*)  d_in[1];
    const int*   p2m  = (const int*)  d_in[2];
    const float* sdp  = (const float*)d_in[3];
    const float* wemb = (const float*)d_in[4];
    const float* p1e  = (const float*)d_in[5];
    const float* p2e  = (const float*)d_in[6];
    const float* w11  = (const float*)d_in[7];
    const float* b11  = (const float*)d_in[8];
    const float* w13  = (const float*)d_in[9];
    const float* b13  = (const float*)d_in[10];
    const float* w15  = (const float*)d_in[11];
    const float* b15  = (const float*)d_in[12];
    const float* w2a  = (const float*)d_in[13];
    const float* b2a  = (const float*)d_in[14];
    const float* w2b  = (const float*)d_in[15];
    const float* b2b  = (const float*)d_in[16];
    const float* d1w  = (const float*)d_in[17];
    const float* d1b  = (const float*)d_in[18];
    const float* d2w  = (const float*)d_in[19];
    const float* d2b  = (const float*)d_in[20];
    const float* d3w  = (const float*)d_in[21];
    const float* d3b  = (const float*)d_in[22];

    __half *Xpad, *P, *A2, *W1, *W3, *W5, *W2a, *W2b;
    float *O3;
    cudaGetSymbolAddress((void**)&Xpad, g_Xpad);
    cudaGetSymbolAddress((void**)&P,   g_P);
    cudaGetSymbolAddress((void**)&A2,  g_A2);
    cudaGetSymbolAddress((void**)&O3,  g_O3);
    cudaGetSymbolAddress((void**)&W1,  g_W1);
    cudaGetSymbolAddress((void**)&W3,  g_W3);
    cudaGetSymbolAddress((void**)&W5,  g_W5);
    cudaGetSymbolAddress((void**)&W2a, g_W2a);
    cudaGetSymbolAddress((void**)&W2b, g_W2b);

    const int SMEM = 3 * STAGEH * 2;   // 110592 B (3 stages)
    cudaFuncSetAttribute(gemm_tri<100>, cudaFuncAttributeMaxDynamicSharedMemorySize, SMEM);
    cudaFuncSetAttribute(gemm_one<50>,  cudaFuncAttributeMaxDynamicSharedMemorySize, SMEM);

    // fused init: weight re-layout + Xpad build, one exactly-sized launch
    init_fused<<<NB_ALL, 256>>>(w11, w13, w15, w2a, w2b,
                                tok, p1m, p2m, sdp, wemb, p1e, p2e);

    long sBX = (long)XROWS * XC;

    // conv1 (x3) + relu + pool(2) fused -> P[b][p][PSTR] half, one launch
    GArgs gc5 = { W5, b15, Xpad,          P, 100, K5P, sBX, XC,
                  50L * PSTR, PSTR, 200, 1, 1, 1 };
    GArgs gc3 = { W3, b13, Xpad + XC,     P, 100, K3P, sBX, XC,
                  50L * PSTR, PSTR, 100, 1, 1, 1 };
    GArgs gc1 = { W1, b11, Xpad + 2 * XC, P, 100, K1P, sBX, XC,
                  50L * PSTR, PSTR, 0, 1, 1, 1 };
    gemm_tri<100><<<dim3(400, 3), 256, SMEM>>>(gc5, gc3, gc1);

    // conv2a (1x1) -> A2 half (padded rows 0,51 stay zero)
    GArgs g2a = { W2a, b2a, P, A2 + 200, 200, K2AP, 50L * PSTR, PSTR,
                  10400, 200, 0, 0, 1, 0 };
    gemm_one<50><<<dim3(200, 2), 256, SMEM>>>(g2a);

    // conv2b (kw=3, pad=1) + relu -> O3 float
    GArgs g2b = { W2b, b2b, A2, O3, 300, K2BP, 10400, 200,
                  15000, 300, 0, 1, 0, 0 };
    gemm_one<50><<<dim3(200, 3), 256, SMEM>>>(g2b);

    pool_fc<<<BATCH, 128>>>(d1w, d1b, d2w, d2b, d3w, d3b, (float*)d_out);
}